// round 15
// baseline (speedup 1.0000x reference)
#include <cuda_runtime.h>
#include <cuda_fp16.h>
#include <cstdint>
#include <float.h>

#define NB 2
#define NN 512
#define NH 8
#define CH 128      // n_head * head_hidden
#define EH 64       // edge hidden
#define QKVW 384
#define TJM 64      // j-rows per tile (MMA M)
#define NT (NB * NN * (NN / TJM))   // 8192 tiles
#define EGRID 296   // 2 CTAs per SM

// Scratch (device globals)
__device__ float g_QKV[NB * NN * QKVW];              // q|k|v per node row
__device__ float g_LOG[(size_t)NB * NN * NN * NH];   // attention logits
__device__ uint32_t g_WeP[32 * 136];                 // We fp16x2 [k2=32][c=128] stride 136

// ---------------------------------------------------------------------------
// helpers
// ---------------------------------------------------------------------------
__device__ __forceinline__ uint32_t pack_f16x2(float lo, float hi) {
    uint32_t d;
    asm("cvt.rn.f16x2.f32 %0, %1, %2;" : "=r"(d) : "f"(hi), "f"(lo));
    return d;
}

__device__ __forceinline__ void mma_f16(float* c,
    uint32_t a0, uint32_t a1, uint32_t a2, uint32_t a3,
    uint32_t b0, uint32_t b1)
{
    asm volatile(
        "mma.sync.aligned.m16n8k16.row.col.f32.f16.f16.f32 "
        "{%0,%1,%2,%3}, {%4,%5,%6,%7}, {%8,%9}, {%0,%1,%2,%3};"
        : "+f"(c[0]), "+f"(c[1]), "+f"(c[2]), "+f"(c[3])
        : "r"(a0), "r"(a1), "r"(a2), "r"(a3), "r"(b0), "r"(b1));
}

__device__ __forceinline__ uint32_t smem_u32(const void* p) {
    uint32_t a;
    asm("{ .reg .u64 t; cvta.to.shared.u64 t, %1; cvt.u32.u64 %0, t; }"
        : "=r"(a) : "l"(p));
    return a;
}
__device__ __forceinline__ void cp16(uint32_t smaddr, const void* g) {
    asm volatile("cp.async.cg.shared.global [%0], [%1], 16;"
                 :: "r"(smaddr), "l"(g) : "memory");
}
#define CP_COMMIT() asm volatile("cp.async.commit_group;" ::: "memory")
#define CP_WAIT0()  asm volatile("cp.async.wait_group 0;" ::: "memory")

// SMEM map (u32 units), 96 KB total -> 2 CTAs/SM.
// A2 triple-duty: raw fp16x2 [64][68] (phase 2 input), then fp32 output
// staging [64][68] (after phase-2 complete, barrier-protected).
#define OFF_B1   0        // 4352   We fp16x2 [32][136]
#define OFF_A1   4352     // 2304   edge tile fp16x2 [64][36]
#define OFF_A2   6656     // 4352   raw fp16x2 / output stage [64][68]
#define OFF_P    11008    // 4096   fp32 edge tile staging [64][64]
#define OFF_K    15104    // 8704   K tile fp32 [64][136]
#define OFF_QS   23808    // 128 floats
#define OFF_BES  23936    // 128 floats
#define OFF_LG   24064    // 512    logits stage [64 rows][8 heads] fp32
#define SMEM_U32 24576    // 98304 bytes

// ---------------------------------------------------------------------------
// Kernel P: We -> packed fp16x2 along k
// ---------------------------------------------------------------------------
__global__ void prep_kernel(const float* __restrict__ We) {
    int t = blockIdx.x * 256 + threadIdx.x;   // 0..4095
    if (t < 32 * 128) {
        int k2 = t >> 7, c = t & 127;
        g_WeP[k2 * 136 + c] = pack_f16x2(We[(2 * k2) * CH + c], We[(2 * k2 + 1) * CH + c]);
    }
}

// ---------------------------------------------------------------------------
// Kernel A: qkv = x @ Wqkv + bqkv.  128 blocks x 384 threads, 8 rows/block.
// ---------------------------------------------------------------------------
__global__ void __launch_bounds__(QKVW) qkv_kernel(
    const float* __restrict__ x, const float* __restrict__ W,
    const float* __restrict__ bias)
{
    __shared__ float xs[8 * CH];
    const int t = threadIdx.x;
    const int r0 = blockIdx.x * 8;

    for (int i = t; i < 8 * CH; i += QKVW) xs[i] = x[r0 * CH + i];
    float bcol = bias[t];
    __syncthreads();

    float acc[8];
#pragma unroll
    for (int r = 0; r < 8; r++) acc[r] = bcol;

#pragma unroll 4
    for (int k = 0; k < CH; k += 4) {
        float w0 = __ldg(W + (k + 0) * QKVW + t);
        float w1 = __ldg(W + (k + 1) * QKVW + t);
        float w2 = __ldg(W + (k + 2) * QKVW + t);
        float w3 = __ldg(W + (k + 3) * QKVW + t);
#pragma unroll
        for (int r = 0; r < 8; r++) {
            float4 xv = *(const float4*)(xs + r * CH + k);
            acc[r] = fmaf(xv.x, w0, acc[r]);
            acc[r] = fmaf(xv.y, w1, acc[r]);
            acc[r] = fmaf(xv.z, w2, acc[r]);
            acc[r] = fmaf(xv.w, w3, acc[r]);
        }
    }
#pragma unroll
    for (int r = 0; r < 8; r++) g_QKV[(r0 + r) * QKVW + t] = acc[r];
}

// ---------------------------------------------------------------------------
// Kernel B: persistent fused edge pipeline, fp16 mma (fp32 accum).
// TJM=64, 256 threads, 2 CTAs/SM. All global outputs smem-staged and
// written fully coalesced.
// ---------------------------------------------------------------------------
__global__ void __launch_bounds__(256, 2) edge_mma_kernel(
    const float* __restrict__ edge_attr,
    const float* __restrict__ be, const float* __restrict__ beo,
    const float* __restrict__ Weo,
    float* __restrict__ edge_out)
{
    extern __shared__ uint32_t smu[];
    float* qs  = (float*)(smu + OFF_QS);
    float* bes = (float*)(smu + OFF_BES);
    float* ksm = (float*)(smu + OFF_K);
    float* lsm = (float*)(smu + OFF_LG);
    float* osm = (float*)(smu + OFF_A2);
    const uint32_t sb = smem_u32(smu);
    const uint32_t p_sm = sb + OFF_P * 4;
    const uint32_t k_sm = sb + OFF_K * 4;

    const int t = threadIdx.x, lane = t & 31, w = t >> 5;   // 8 warps
    const int g = lane >> 2, c4 = lane & 3;
    // phase 1 mapping: 2m x 4n warp grid over [64j x 128c]
    const int m0 = (w & 1) * 32, n0 = (w >> 1) * 32;
    const int n0h = n0 >> 1;                    // u32 col base in A2
    const int wn = w >> 1;                      // head-pair group
    // phase 2 mapping: 4(eo) x 2(j) warp grid over [64eo x 64j]
    const int eo0 = (w & 3) * 16, jn = (w >> 2) * 32;

    // ---- one-time: We tile to smem, bias, persistent Weo^T fp16 fragments ----
    for (int i = t; i < 32 * 136; i += 256) smu[OFF_B1 + i] = g_WeP[i];
    if (t < CH) bes[t] = be[t];

    const float beo0 = beo[eo0 + g], beo1 = beo[eo0 + g + 8];

    uint32_t areg[8][4];                        // Weo^T [64eo][128k] fragments
#pragma unroll
    for (int ks = 0; ks < 8; ks++) {
        int k2a = ks * 8 + c4;                  // packed-k index (pairs)
        int k2b = k2a + 4;
        areg[ks][0] = pack_f16x2(__ldg(Weo + (2 * k2a)     * EH + eo0 + g),
                                 __ldg(Weo + (2 * k2a + 1) * EH + eo0 + g));
        areg[ks][1] = pack_f16x2(__ldg(Weo + (2 * k2a)     * EH + eo0 + g + 8),
                                 __ldg(Weo + (2 * k2a + 1) * EH + eo0 + g + 8));
        areg[ks][2] = pack_f16x2(__ldg(Weo + (2 * k2b)     * EH + eo0 + g),
                                 __ldg(Weo + (2 * k2b + 1) * EH + eo0 + g));
        areg[ks][3] = pack_f16x2(__ldg(Weo + (2 * k2b)     * EH + eo0 + g + 8),
                                 __ldg(Weo + (2 * k2b + 1) * EH + eo0 + g + 8));
    }

    // ---- prefetch first tile: edge + K ----
    int tile = blockIdx.x;
    if (tile < NT) {
        int bi = tile >> 3, jt = tile & 7, b0v = bi >> 9;
        const float4* src = (const float4*)(edge_attr + ((size_t)bi * NN + jt * TJM) * EH);
#pragma unroll
        for (int s = 0; s < 4; s++) {            // 1024 float4
            int fi = t + s * 256;
            cp16(p_sm + fi * 16, src + fi);
        }
        const float* kbase = g_QKV + ((size_t)(b0v * NN + jt * TJM)) * QKVW + CH;
#pragma unroll
        for (int s = 0; s < 8; s++) {            // 2048 float4
            int fi = t + s * 256;
            int row = fi >> 5, cq = fi & 31;
            cp16(k_sm + (row * 136 + cq * 4) * 4, kbase + (size_t)row * QKVW + cq * 4);
        }
    }
    CP_COMMIT();

    for (; tile < NT; tile += EGRID) {
        const int bi = tile >> 3, jt = tile & 7;
        const int jbase = jt * TJM;

        CP_WAIT0();
        __syncthreads();       // staging P + K valid; prior tile done

        // ---- staged fp32 tile -> A1 fp16x2 [64][36]; q row ----
        {
            const float4* Pf4 = (const float4*)(smu + OFF_P);
#pragma unroll
            for (int s = 0; s < 4; s++) {
                int fi = t + s * 256;              // 1024 float4
                int row = fi >> 4, q4 = fi & 15;
                float4 v = Pf4[fi];
                *(uint2*)(smu + OFF_A1 + row * 36 + q4 * 2) =
                    make_uint2(pack_f16x2(v.x, v.y), pack_f16x2(v.z, v.w));
            }
            if (t < CH) qs[t] = g_QKV[bi * QKVW + t];
        }
        __syncthreads();       // A1/qs ready; staging P consumed

        // ---- prefetch next edge tile into P ----
        {
            int nt2 = tile + EGRID;
            if (nt2 < NT) {
                int nbi = nt2 >> 3, njt = nt2 & 7;
                const float4* src = (const float4*)(edge_attr + ((size_t)nbi * NN + njt * TJM) * EH);
#pragma unroll
                for (int s = 0; s < 4; s++) {
                    int fi = t + s * 256;
                    cp16(p_sm + fi * 16, src + fi);
                }
            }
            CP_COMMIT();
        }

        // ---- phase 1: e[64,128] = A1[64,64] x We, 4 fp16 k16-steps ----
        float acc[2][4][4];
#pragma unroll
        for (int mf = 0; mf < 2; mf++)
#pragma unroll
            for (int nf = 0; nf < 4; nf++)
#pragma unroll
                for (int i = 0; i < 4; i++) acc[mf][nf][i] = 0.f;

#pragma unroll
        for (int ks = 0; ks < 4; ks++) {
            const int kb = ks * 8;                   // u32 offset (8 u32 = 16 k)
            uint32_t a[2][4];
#pragma unroll
            for (int mf = 0; mf < 2; mf++) {
                int r0 = OFF_A1 + (m0 + mf * 16 + g) * 36 + kb + c4;
                int r1 = r0 + 8 * 36;
                a[mf][0] = smu[r0];     a[mf][1] = smu[r1];
                a[mf][2] = smu[r0 + 4]; a[mf][3] = smu[r1 + 4];
            }
#pragma unroll
            for (int nf = 0; nf < 4; nf++) {
                int bidx = OFF_B1 + (kb + c4) * 136 + n0 + nf * 8 + g;
                uint32_t b0 = smu[bidx], b1 = smu[bidx + 4 * 136];
#pragma unroll
                for (int mf = 0; mf < 2; mf++)
                    mma_f16(acc[mf][nf], a[mf][0], a[mf][1], a[mf][2], a[mf][3], b0, b1);
            }
        }

        // ---- epilogue 1: raw = (e+be)*q*k (K from smem), logits -> lsm;
        //      raw fp16x2 -> A2 ----
#pragma unroll
        for (int mf = 0; mf < 2; mf++) {
#pragma unroll
            for (int cih = 0; cih < 2; cih++) {
                int r = m0 + mf * 16 + g + cih * 8;
                const float* kr = ksm + r * 136;
                float lg0 = 0.f, lg1 = 0.f;
#pragma unroll
                for (int nf = 0; nf < 4; nf++) {
                    int c = n0 + nf * 8 + 2 * c4;
                    float2 kk = *(const float2*)(kr + c);
                    float2 qq = *(const float2*)(qs + c);
                    float2 bb = *(const float2*)(bes + c);
                    float r0 = (acc[mf][nf][cih * 2 + 0] + bb.x) * qq.x * kk.x;
                    float r1 = (acc[mf][nf][cih * 2 + 1] + bb.y) * qq.y * kk.y;
                    smu[OFF_A2 + r * 68 + n0h + nf * 4 + c4] = pack_f16x2(r0, r1);
                    float p = r0 + r1;
                    if (nf < 2) lg0 += p; else lg1 += p;
                }
                lg0 += __shfl_xor_sync(0xffffffffu, lg0, 1);
                lg0 += __shfl_xor_sync(0xffffffffu, lg0, 2);
                lg1 += __shfl_xor_sync(0xffffffffu, lg1, 1);
                lg1 += __shfl_xor_sync(0xffffffffu, lg1, 2);
                if (c4 == 0) {
                    *(float2*)(lsm + r * NH + 2 * wn) =
                        make_float2(lg0 * 0.25f, lg1 * 0.25f);
                }
            }
        }
        __syncthreads();       // raw + lsm complete; K staging consumed

        // ---- coalesced logits write (2 KB contiguous) ----
        if (t < 128) {
            ((float4*)(g_LOG + ((size_t)bi * NN + jbase) * NH))[t] =
                ((const float4*)lsm)[t];
        }

        // ---- prefetch next K tile (lands during phase 2) ----
        {
            int nt2 = tile + EGRID;
            if (nt2 < NT) {
                int nbi = nt2 >> 3, njt = nt2 & 7, nb = nbi >> 9;
                const float* kbase = g_QKV + ((size_t)(nb * NN + njt * TJM)) * QKVW + CH;
#pragma unroll
                for (int s = 0; s < 8; s++) {
                    int fi = t + s * 256;
                    int row = fi >> 5, cq = fi & 31;
                    cp16(k_sm + (row * 136 + cq * 4) * 4, kbase + (size_t)row * QKVW + cq * 4);
                }
            }
            CP_COMMIT();
        }

        // ---- phase 2 (transposed): out^T[64,64] = Weo^T x raw^T, 8 steps ----
        float o[4][4];
#pragma unroll
        for (int nf = 0; nf < 4; nf++)
#pragma unroll
            for (int i = 0; i < 4; i++) o[nf][i] = 0.f;

#pragma unroll
        for (int ks = 0; ks < 8; ks++) {
            const int kb = ks * 8;
#pragma unroll
            for (int nf = 0; nf < 4; nf++) {
                int bidx = OFF_A2 + (jn + nf * 8 + g) * 68 + kb + c4;
                uint32_t b0 = smu[bidx], b1 = smu[bidx + 4];
                mma_f16(o[nf], areg[ks][0], areg[ks][1], areg[ks][2], areg[ks][3], b0, b1);
            }
        }
        __syncthreads();       // all phase-2 A2(raw) reads done

        // ---- epilogue 2: stage o+beo into A2 as fp32 [64][68] ----
#pragma unroll
        for (int nf = 0; nf < 4; nf++) {
            int j = jn + nf * 8 + 2 * c4;
            osm[j * 68 + eo0 + g]           = o[nf][0] + beo0;
            osm[(j + 1) * 68 + eo0 + g]     = o[nf][1] + beo0;
            osm[j * 68 + eo0 + g + 8]       = o[nf][2] + beo1;
            osm[(j + 1) * 68 + eo0 + g + 8] = o[nf][3] + beo1;
        }
        __syncthreads();

        // ---- fully coalesced edge_out store (warp = 2 complete rows) ----
        {
            float* dst = edge_out + ((size_t)bi * NN + jbase) * EH;
#pragma unroll
            for (int s = 0; s < 4; s++) {
                int fi = t + s * 256;              // 1024 float4
                int row = fi >> 4, q4 = fi & 15;
                float4 v = *(const float4*)(osm + row * 68 + q4 * 4);
                *(float4*)(dst + row * EH + q4 * 4) = v;
            }
        }
    }
}

// ---------------------------------------------------------------------------
// Kernel C: masked softmax + att@V + node projection, 2 (b,i) rows per block
// (V re-reads amortized 2x -> halves the L2-bound traffic).
// ---------------------------------------------------------------------------
__global__ void __launch_bounds__(512) softmax_node_kernel(
    const int* __restrict__ mask,
    const float* __restrict__ Wno, const float* __restrict__ bno,
    float* __restrict__ node_out)
{
    __shared__ float ls[2][NN * 9];        // stride 9: conflict-free
    __shared__ float partial[2][16 * 132]; // also reused as np
    __shared__ float redm[2][2][NH], reds[2][2][NH];
    __shared__ float node_s[2][CH];
    __shared__ float invs[2][NH];
    __shared__ int msk[NN];

    int bi0 = blockIdx.x * 2;        // first (b,i); both share b
    int b = bi0 >> 9, t = threadIdx.x;

    if (t < NN) msk[t] = mask[b * NN + t];
    __syncthreads();

#pragma unroll
    for (int ii = 0; ii < 2; ii++) {
        const float4* Lp = (const float4*)(g_LOG + (size_t)(bi0 + ii) * NN * NH);
#pragma unroll
        for (int s = 0; s < 2; s++) {
            int fi = t + s * 512;
            float4 v = Lp[fi];
            int j = fi >> 1, hb = (fi & 1) * 4;
            if (!msk[j]) { v.x = v.y = v.z = v.w = -FLT_MAX; }
            ls[ii][j * 9 + hb + 0] = v.x;
            ls[ii][j * 9 + hb + 1] = v.y;
            ls[ii][j * 9 + hb + 2] = v.z;
            ls[ii][j * 9 + hb + 3] = v.w;
        }
    }
    __syncthreads();

    {   // softmax: 2 warps per head (warp w: head w&7, j-half w>>3), both i
        int wH = (t >> 5) & 7, half = t >> 8, l = t & 31;
        int jb = half * 256 + l;
        float m[2];
#pragma unroll
        for (int ii = 0; ii < 2; ii++) {
            float mm = -FLT_MAX;
#pragma unroll
            for (int k = 0; k < 8; k++)
                mm = fmaxf(mm, ls[ii][(jb + 32 * k) * 9 + wH]);
#pragma unroll
            for (int off = 16; off; off >>= 1)
                mm = fmaxf(mm, __shfl_xor_sync(0xffffffffu, mm, off));
            if (l == 0) redm[ii][half][wH] = mm;
        }
        __syncthreads();
#pragma unroll
        for (int ii = 0; ii < 2; ii++) {
            m[ii] = fmaxf(redm[ii][0][wH], redm[ii][1][wH]);
            float s = 0.f;
#pragma unroll
            for (int k = 0; k < 8; k++) {
                int j = jb + 32 * k;
                float p = __expf(ls[ii][j * 9 + wH] - m[ii]);
                ls[ii][j * 9 + wH] = p;
                s += p;
            }
#pragma unroll
            for (int off = 16; off; off >>= 1)
                s += __shfl_xor_sync(0xffffffffu, s, off);
            if (l == 0) reds[ii][half][wH] = s;
        }
        __syncthreads();
        if (t < 2 * NH) {
            int ii = t >> 3, h = t & 7;
            invs[ii][h] = 1.f / (reds[ii][0][h] + reds[ii][1][h]);
        }
    }

    {   // attention * V: warp wq owns 32 j-rows; each V float4 serves both i
        int wq = t >> 5, l = t & 31, h = l >> 2;
        const float4* Vp = (const float4*)(g_QKV + (size_t)(b * NN + wq * 32) * QKVW + 2 * CH);
        const float* l0 = ls[0] + (wq * 32) * 9 + h;
        const float* l1 = ls[1] + (wq * 32) * 9 + h;
        float4 a0 = make_float4(0.f, 0.f, 0.f, 0.f);
        float4 a1 = make_float4(0.f, 0.f, 0.f, 0.f);
#pragma unroll 8
        for (int j = 0; j < 32; j++) {
            float4 v = __ldg(Vp + (size_t)j * (QKVW / 4) + l);
            float p0 = l0[j * 9], p1 = l1[j * 9];
            a0.x = fmaf(p0, v.x, a0.x); a0.y = fmaf(p0, v.y, a0.y);
            a0.z = fmaf(p0, v.z, a0.z); a0.w = fmaf(p0, v.w, a0.w);
            a1.x = fmaf(p1, v.x, a1.x); a1.y = fmaf(p1, v.y, a1.y);
            a1.z = fmaf(p1, v.z, a1.z); a1.w = fmaf(p1, v.w, a1.w);
        }
        *(float4*)(partial[0] + wq * 132 + 4 * l) = a0;
        *(float4*)(partial[1] + wq * 132 + 4 * l) = a1;
    }
    __syncthreads();

    if (t < 2 * CH) {
        int ii = t >> 7, c = t & 127;
        float s = 0.f;
#pragma unroll
        for (int p = 0; p < 16; p++) s += partial[ii][p * 132 + c];
        node_s[ii][c] = s * invs[ii][c >> 4];
    }
    __syncthreads();

    {   // node @ Wno: warp ws owns k-slice; each Wno float4 serves both i
        int ws = t >> 5, l = t & 31;
        float4 o0 = make_float4(0.f, 0.f, 0.f, 0.f);
        float4 o1 = make_float4(0.f, 0.f, 0.f, 0.f);
#pragma unroll
        for (int k = 0; k < 8; k++) {
            float s0 = node_s[0][ws * 8 + k], s1 = node_s[1][ws * 8 + k];
            float4 wv = __ldg((const float4*)(Wno + (ws * 8 + k) * CH) + l);
            o0.x = fmaf(s0, wv.x, o0.x); o0.y = fmaf(s0, wv.y, o0.y);
            o0.z = fmaf(s0, wv.z, o0.z); o0.w = fmaf(s0, wv.w, o0.w);
            o1.x = fmaf(s1, wv.x, o1.x); o1.y = fmaf(s1, wv.y, o1.y);
            o1.z = fmaf(s1, wv.z, o1.z); o1.w = fmaf(s1, wv.w, o1.w);
        }
        __syncthreads();       // node_s consumed; reuse partial as np
        *(float4*)(partial[0] + ws * 132 + 4 * l) = o0;
        *(float4*)(partial[1] + ws * 132 + 4 * l) = o1;
    }
    __syncthreads();

    if (t < 2 * CH) {
        int ii = t >> 7, c = t & 127;
        float r = bno[c];
#pragma unroll
        for (int p = 0; p < 16; p++) r += partial[ii][p * 132 + c];
        node_out[(size_t)(bi0 + ii) * CH + c] = r;
    }
}

// ---------------------------------------------------------------------------
extern "C" void kernel_launch(void* const* d_in, const int* in_sizes, int n_in,
                              void* d_out, int out_size)
{
    const float* x         = (const float*)d_in[0];
    const float* edge_attr = (const float*)d_in[1];
    const int*   mask      = (const int*)d_in[2];
    const float* Wqkv      = (const float*)d_in[3];
    const float* bqkv      = (const float*)d_in[4];
    const float* We        = (const float*)d_in[5];
    const float* be        = (const float*)d_in[6];
    const float* Wno       = (const float*)d_in[7];
    const float* bno       = (const float*)d_in[8];
    const float* Weo       = (const float*)d_in[9];
    const float* beo       = (const float*)d_in[10];

    float* out      = (float*)d_out;
    float* node_out = out;                       // (2,512,128)
    float* edge_out = out + NB * NN * CH;        // (2,512,512,64)

    prep_kernel<<<16, 256>>>(We);
    qkv_kernel<<<128, QKVW>>>(x, Wqkv, bqkv);

    size_t shmem = SMEM_U32 * sizeof(uint32_t);  // 98304 B
    cudaFuncSetAttribute(edge_mma_kernel,
                         cudaFuncAttributeMaxDynamicSharedMemorySize, (int)shmem);
    edge_mma_kernel<<<EGRID, 256, shmem>>>(edge_attr, be, beo, Weo, edge_out);

    softmax_node_kernel<<<NB * NN / 2, 512>>>(mask, Wno, bno, node_out);
}